// round 12
// baseline (speedup 1.0000x reference)
#include <cuda_runtime.h>
#include <cstdint>

// ---------------------------------------------------------------------------
// Problem constants
// ---------------------------------------------------------------------------
#define BB 64
#define CC 3
#define HH 384
#define WW 384
#define HW (HH * WW)            // 147456
#define CHW (CC * HW)           // 442368
#define NTOT (BB * CHW)         // 28311552
// 16-float chunks; W % 16 == 0 so a chunk never straddles a row
#define CPR  (WW / 16)          // chunks per row      = 24
#define CPC  (HW / 16)          // chunks per channel  = 9216
#define CPI  (CHW / 16)         // chunks per image    = 27648
#define NCH  (NTOT / 16)        // total chunks        = 1769472
#define BLK  256
#define KITER 6                 // chunks per thread
#define CHUNKS_PER_BLK (BLK * KITER)        // 1536
#define NBLK (NCH / CHUNKS_PER_BLK)         // 1152 blocks, exact
#define BLOCKS_PER_IMG (CPI / CHUNKS_PER_BLK)  // 18, exact -> 1 image/block

// ---------------------------------------------------------------------------
// constexpr threefry2x32 (JAX schedule) — compile-time child keys of
// jax.random.split(jax.random.key(42), 6), partitionable: child i = tf(k,0,i)
// ---------------------------------------------------------------------------
constexpr unsigned long long tf_pair_ce(unsigned k0, unsigned k1,
                                        unsigned x0, unsigned x1) {
    unsigned k2 = k0 ^ k1 ^ 0x1BD11BDAu;
    x0 += k0; x1 += k1;
    const int rots[5][4] = {{13,15,26,6},{17,29,16,24},{13,15,26,6},
                            {17,29,16,24},{13,15,26,6}};
    const unsigned ka[5] = {k1, k2, k0, k1, k2};
    const unsigned kb[5] = {k2, k0, k1, k2, k0};
    for (int g = 0; g < 5; ++g) {
        for (int j = 0; j < 4; ++j) {
            x0 += x1;
            int r = rots[g][j];
            x1 = (x1 << r) | (x1 >> (32 - r));
            x1 ^= x0;
        }
        x0 += ka[g];
        x1 += kb[g] + (unsigned)(g + 1);
    }
    return ((unsigned long long)x0 << 32) | (unsigned long long)x1;
}

constexpr unsigned long long KP_ = tf_pair_ce(0u, 42u, 0u, 0u);
constexpr unsigned long long KA_ = tf_pair_ce(0u, 42u, 0u, 1u);
constexpr unsigned long long KR_ = tf_pair_ce(0u, 42u, 0u, 2u);
constexpr unsigned long long KT_ = tf_pair_ce(0u, 42u, 0u, 3u);
constexpr unsigned long long KL_ = tf_pair_ce(0u, 42u, 0u, 4u);
constexpr unsigned long long KN_ = tf_pair_ce(0u, 42u, 0u, 5u);

#define KHI(k) ((unsigned)((k) >> 32))
#define KLO(k) ((unsigned)((k) & 0xFFFFFFFFull))

// ---------------------------------------------------------------------------
// Device threefry: bits(i) = out0 ^ out1 of threefry(key, 0, i)
// ---------------------------------------------------------------------------
__device__ __forceinline__ unsigned tf_bits(unsigned k0, unsigned k1, unsigned ctr) {
    unsigned k2 = k0 ^ k1 ^ 0x1BD11BDAu;
    unsigned x0 = k0;
    unsigned x1 = ctr + k1;
#define TFR(r) { x0 += x1; x1 = __funnelshift_l(x1, x1, (r)); x1 ^= x0; }
    TFR(13) TFR(15) TFR(26) TFR(6)
    x0 += k1; x1 += k2 + 1u;
    TFR(17) TFR(29) TFR(16) TFR(24)
    x0 += k2; x1 += k0 + 2u;
    TFR(13) TFR(15) TFR(26) TFR(6)
    x0 += k0; x1 += k1 + 3u;
    TFR(17) TFR(29) TFR(16) TFR(24)
    x0 += k1; x1 += k2 + 4u;
    TFR(13) TFR(15) TFR(26) TFR(6)
    x0 += k2; x1 += k0 + 5u;
#undef TFR
    return x0 ^ x1;
}

__device__ __forceinline__ float u01(unsigned bits) {
    return __uint_as_float((bits >> 9) | 0x3F800000u) - 1.0f;
}

// ---------------------------------------------------------------------------
// Per-sample erase rectangle {top, bottom, left, right}; empty when invalid.
// Same arithmetic as the reference -> bit-identical decisions.
// ---------------------------------------------------------------------------
__device__ __forceinline__ int4 compute_rect(int b) {
    float up = u01(tf_bits(KHI(KP_), KLO(KP_), (unsigned)b));
    bool apply = (up <= 0.5f);

    float ua = u01(tf_bits(KHI(KA_), KLO(KA_), (unsigned)b));
    const float RA = 0.33f - 0.02f;
    float ta_u = fmaxf(0.02f, __fadd_rn(__fmul_rn(ua, RA), 0.02f));
    float ta = __fmul_rn(ta_u, 147456.0f);

    float ur = u01(tf_bits(KHI(KR_), KLO(KR_), (unsigned)b));
    const float RR = 3.3f - 0.3f;
    float ar = fmaxf(0.3f, __fadd_rn(__fmul_rn(ur, RR), 0.3f));

    int h_e = (int)rintf(__fsqrt_rn(__fmul_rn(ta, ar)));
    int w_e = (int)rintf(__fsqrt_rn(__fdiv_rn(ta, ar)));

    bool valid = apply && (h_e < HH) && (w_e < WW);

    float ut = u01(tf_bits(KHI(KT_), KLO(KT_), (unsigned)b));
    float ul = u01(tf_bits(KHI(KL_), KLO(KL_), (unsigned)b));
    int top  = (int)floorf(__fmul_rn(ut, (float)(HH - h_e + 1)));
    int left = (int)floorf(__fmul_rn(ul, (float)(WW - w_e + 1)));

    int4 r;
    if (valid) { r.x = top; r.y = top + h_e; r.z = left; r.w = left + w_e; }
    else       { r.x = 0;   r.y = 0;         r.z = 0;    r.w = 0; }
    return r;
}

// ---------------------------------------------------------------------------
// Noise at global element index i (JAX normal = sqrt(2)*erfinv(uniform(-1,1)))
// ---------------------------------------------------------------------------
__device__ __forceinline__ float noise_at(unsigned i) {
    unsigned bits = tf_bits(KHI(KN_), KLO(KN_), i);
    float u = u01(bits);
    const float LO = -0.99999994039535522461f;    // nextafter(-1,0) f32
    float v = fmaxf(LO, __fadd_rn(__fmul_rn(u, 2.0f), LO));
    return __uint_as_float(0x3FB504F3u) * erfinvf(v);
}

// ---------------------------------------------------------------------------
// Load 4 consecutive float4 (one 16-float chunk) for chunk index g
// ---------------------------------------------------------------------------
__device__ __forceinline__ void load_chunk(float4* dst, const float4* __restrict__ x,
                                           unsigned g) {
    const float4* xp = x + (size_t)g * 4;
    dst[0] = xp[0];
    dst[1] = xp[1];
    dst[2] = xp[2];
    dst[3] = xp[3];
}

// ---------------------------------------------------------------------------
// Process one chunk held in `o[16]` and store it.
//  r  = chunk index within image; g = global chunk index.
// ---------------------------------------------------------------------------
__device__ __forceinline__ void process_store(float* o, int r, unsigned g,
                                              int4 rc,
                                              float iv0, float iv1, float iv2,
                                              float bs0, float bs1, float bs2,
                                              float4* __restrict__ out) {
    int c  = r / CPC;
    int r0 = r - c * CPC;
    int h  = r0 / CPR;
    int w0 = (r0 - h * CPR) << 4;

    float inv  = (c == 0) ? iv0 : ((c == 1) ? iv1 : iv2);
    float bias = (c == 0) ? bs0 : ((c == 1) ? bs1 : bs2);

    #pragma unroll
    for (int j = 0; j < 16; ++j)
        o[j] = fmaf(o[j], inv, bias);

    if (h >= rc.x && h < rc.y && w0 + 15 >= rc.z && w0 < rc.w) {
        unsigned e0 = g * 16u;
        #pragma unroll
        for (int j = 0; j < 16; ++j) {
            int w = w0 + j;
            if (w >= rc.z && w < rc.w) o[j] = noise_at(e0 + (unsigned)j);
        }
    }

    float4* c4 = reinterpret_cast<float4*>(o);
    float4* op = out + (size_t)g * 4;
    op[0] = c4[0];
    op[1] = c4[1];
    op[2] = c4[2];
    op[3] = c4[3];
}

// ---------------------------------------------------------------------------
// Double-buffered register pipeline: 6 chunks/thread, at most 4 LDG.128 in
// flight per thread at any time (the proven sweet spot), with the next
// chunk's loads overlapping the current chunk's FMA/erase/store.
// Outer loop is unroll-1 over A/B pairs so ptxas cannot re-batch loads.
// ---------------------------------------------------------------------------
__global__ void __launch_bounds__(BLK)
erase_kernel(const float4* __restrict__ x,
             const float* __restrict__ mean,
             const float* __restrict__ stdv,
             float4* __restrict__ out) {
    __shared__ int4 s_rect;

    const int t  = threadIdx.x;
    const int b  = blockIdx.x / BLOCKS_PER_IMG;
    const int ci0 = (blockIdx.x - b * BLOCKS_PER_IMG) * CHUNKS_PER_BLK + t;
    const unsigned g0 = (unsigned)blockIdx.x * CHUNKS_PER_BLK + (unsigned)t;

    alignas(16) float bufA[16], bufB[16];

    // get the first load batch in flight before anything else
    load_chunk(reinterpret_cast<float4*>(bufA), x, g0);

    if (t == 0) s_rect = compute_rect(b);

    float iv0 = 1.0f / __ldg(&stdv[0]);
    float iv1 = 1.0f / __ldg(&stdv[1]);
    float iv2 = 1.0f / __ldg(&stdv[2]);
    float bs0 = -__ldg(&mean[0]) * iv0;
    float bs1 = -__ldg(&mean[1]) * iv1;
    float bs2 = -__ldg(&mean[2]) * iv2;

    __syncthreads();
    const int4 rc = s_rect;

    #pragma unroll 1
    for (int kk = 0; kk < KITER / 2; ++kk) {
        const int k = 2 * kk;

        // loads for chunk k+1 fly while chunk k is processed
        load_chunk(reinterpret_cast<float4*>(bufB), x, g0 + (unsigned)(k + 1) * BLK);
        process_store(bufA, ci0 + k * BLK, g0 + (unsigned)k * BLK,
                      rc, iv0, iv1, iv2, bs0, bs1, bs2, out);

        // loads for chunk k+2 fly while chunk k+1 is processed
        if (kk + 1 < KITER / 2)
            load_chunk(reinterpret_cast<float4*>(bufA), x,
                       g0 + (unsigned)(k + 2) * BLK);
        process_store(bufB, ci0 + (k + 1) * BLK, g0 + (unsigned)(k + 1) * BLK,
                      rc, iv0, iv1, iv2, bs0, bs1, bs2, out);
    }
}

// ---------------------------------------------------------------------------
// Launch
// ---------------------------------------------------------------------------
extern "C" void kernel_launch(void* const* d_in, const int* in_sizes, int n_in,
                              void* d_out, int out_size) {
    const float4* x   = (const float4*)d_in[0];
    const float*  mn  = (const float*)d_in[1];
    const float*  sd  = (const float*)d_in[2];
    float4*       out = (float4*)d_out;

    erase_kernel<<<NBLK, BLK>>>(x, mn, sd, out);
}

// round 15
// speedup vs baseline: 1.4076x; 1.4076x over previous
#include <cuda_runtime.h>
#include <cstdint>

// ---------------------------------------------------------------------------
// Problem constants
// ---------------------------------------------------------------------------
#define BB 64
#define CC 3
#define HH 384
#define WW 384
#define HW (HH * WW)            // 147456
#define CHW (CC * HW)           // 442368
#define NTOT (BB * CHW)         // 28311552
// 16 floats (64B) per thread; W % 16 == 0 so a chunk never straddles a row
#define CPR  (WW / 16)          // chunks per row      = 24
#define CPC  (HW / 16)          // chunks per channel  = 9216
#define CPI  (CHW / 16)         // chunks per image    = 27648
#define NCH  (NTOT / 16)        // total chunks        = 1769472
#define BLK  256
#define NBLK (NCH / BLK)        // 6912 blocks, exact
#define BLOCKS_PER_IMG (CPI / BLK)   // 108, exact -> one image per block

// ---------------------------------------------------------------------------
// constexpr threefry2x32 (JAX schedule) — compile-time child keys of
// jax.random.split(jax.random.key(42), 6), partitionable: child i = tf(k,0,i)
// ---------------------------------------------------------------------------
constexpr unsigned long long tf_pair_ce(unsigned k0, unsigned k1,
                                        unsigned x0, unsigned x1) {
    unsigned k2 = k0 ^ k1 ^ 0x1BD11BDAu;
    x0 += k0; x1 += k1;
    const int rots[5][4] = {{13,15,26,6},{17,29,16,24},{13,15,26,6},
                            {17,29,16,24},{13,15,26,6}};
    const unsigned ka[5] = {k1, k2, k0, k1, k2};
    const unsigned kb[5] = {k2, k0, k1, k2, k0};
    for (int g = 0; g < 5; ++g) {
        for (int j = 0; j < 4; ++j) {
            x0 += x1;
            int r = rots[g][j];
            x1 = (x1 << r) | (x1 >> (32 - r));
            x1 ^= x0;
        }
        x0 += ka[g];
        x1 += kb[g] + (unsigned)(g + 1);
    }
    return ((unsigned long long)x0 << 32) | (unsigned long long)x1;
}

constexpr unsigned long long KP_ = tf_pair_ce(0u, 42u, 0u, 0u);
constexpr unsigned long long KA_ = tf_pair_ce(0u, 42u, 0u, 1u);
constexpr unsigned long long KR_ = tf_pair_ce(0u, 42u, 0u, 2u);
constexpr unsigned long long KT_ = tf_pair_ce(0u, 42u, 0u, 3u);
constexpr unsigned long long KL_ = tf_pair_ce(0u, 42u, 0u, 4u);
constexpr unsigned long long KN_ = tf_pair_ce(0u, 42u, 0u, 5u);

#define KHI(k) ((unsigned)((k) >> 32))
#define KLO(k) ((unsigned)((k) & 0xFFFFFFFFull))

// ---------------------------------------------------------------------------
// Device threefry: bits(i) = out0 ^ out1 of threefry(key, 0, i)
// ---------------------------------------------------------------------------
__device__ __forceinline__ unsigned tf_bits(unsigned k0, unsigned k1, unsigned ctr) {
    unsigned k2 = k0 ^ k1 ^ 0x1BD11BDAu;
    unsigned x0 = k0;
    unsigned x1 = ctr + k1;
#define TFR(r) { x0 += x1; x1 = __funnelshift_l(x1, x1, (r)); x1 ^= x0; }
    TFR(13) TFR(15) TFR(26) TFR(6)
    x0 += k1; x1 += k2 + 1u;
    TFR(17) TFR(29) TFR(16) TFR(24)
    x0 += k2; x1 += k0 + 2u;
    TFR(13) TFR(15) TFR(26) TFR(6)
    x0 += k0; x1 += k1 + 3u;
    TFR(17) TFR(29) TFR(16) TFR(24)
    x0 += k1; x1 += k2 + 4u;
    TFR(13) TFR(15) TFR(26) TFR(6)
    x0 += k2; x1 += k0 + 5u;
#undef TFR
    return x0 ^ x1;
}

__device__ __forceinline__ float u01(unsigned bits) {
    return __uint_as_float((bits >> 9) | 0x3F800000u) - 1.0f;
}

// ---------------------------------------------------------------------------
// Warp-parallel erase rectangle: the 6 PRNG streams are independent, so
// lanes 0..4 each evaluate one tf_bits (≈60-cycle chain) concurrently and
// share via shfl; every lane then redoes the cheap scalar arithmetic.
// Exactly the reference arithmetic -> bit-identical decisions. No smem,
// no __syncthreads.
// ---------------------------------------------------------------------------
__device__ __forceinline__ int4 compute_rect_warp(int b) {
    unsigned lane = threadIdx.x & 31u;
    unsigned k0, k1;
    switch (lane) {
        case 0:  k0 = KHI(KP_); k1 = KLO(KP_); break;
        case 1:  k0 = KHI(KA_); k1 = KLO(KA_); break;
        case 2:  k0 = KHI(KR_); k1 = KLO(KR_); break;
        case 3:  k0 = KHI(KT_); k1 = KLO(KT_); break;
        default: k0 = KHI(KL_); k1 = KLO(KL_); break;
    }
    float u  = u01(tf_bits(k0, k1, (unsigned)b));
    float up = __shfl_sync(0xFFFFFFFFu, u, 0);
    float ua = __shfl_sync(0xFFFFFFFFu, u, 1);
    float ur = __shfl_sync(0xFFFFFFFFu, u, 2);
    float ut = __shfl_sync(0xFFFFFFFFu, u, 3);
    float ul = __shfl_sync(0xFFFFFFFFu, u, 4);

    bool apply = (up <= 0.5f);

    const float RA = 0.33f - 0.02f;
    float ta_u = fmaxf(0.02f, __fadd_rn(__fmul_rn(ua, RA), 0.02f));
    float ta = __fmul_rn(ta_u, 147456.0f);

    const float RR = 3.3f - 0.3f;
    float ar = fmaxf(0.3f, __fadd_rn(__fmul_rn(ur, RR), 0.3f));

    int h_e = (int)rintf(__fsqrt_rn(__fmul_rn(ta, ar)));
    int w_e = (int)rintf(__fsqrt_rn(__fdiv_rn(ta, ar)));

    bool valid = apply && (h_e < HH) && (w_e < WW);

    int top  = (int)floorf(__fmul_rn(ut, (float)(HH - h_e + 1)));
    int left = (int)floorf(__fmul_rn(ul, (float)(WW - w_e + 1)));

    int4 r;
    if (valid) { r.x = top; r.y = top + h_e; r.z = left; r.w = left + w_e; }
    else       { r.x = 0;   r.y = 0;         r.z = 0;    r.w = 0; }
    return r;
}

// ---------------------------------------------------------------------------
// Noise at global element index i (JAX normal = sqrt(2)*erfinv(uniform(-1,1)))
// ---------------------------------------------------------------------------
__device__ __forceinline__ float noise_at(unsigned i) {
    unsigned bits = tf_bits(KHI(KN_), KLO(KN_), i);
    float u = u01(bits);
    const float LO = -0.99999994039535522461f;    // nextafter(-1,0) f32
    float v = fmaxf(LO, __fadd_rn(__fmul_rn(u, 2.0f), LO));
    return __uint_as_float(0x3FB504F3u) * erfinvf(v);
}

// ---------------------------------------------------------------------------
// Streaming kernel (champion shape): 16 contiguous floats (4x LDG.128) per
// thread, regs~32, occ~80%. Each 256-thread block lies in one image; the
// rect is computed warp-parallel (no barrier, no smem). Stores are
// evict-first (__stcs) since the output stream has zero reuse.
// ---------------------------------------------------------------------------
__global__ void __launch_bounds__(BLK)
erase_kernel(const float4* __restrict__ x,
             const float* __restrict__ mean,
             const float* __restrict__ stdv,
             float4* __restrict__ out) {
    const int t = blockIdx.x * BLK + threadIdx.x;    // chunk id, < NCH
    const int b = blockIdx.x / BLOCKS_PER_IMG;       // image (uniform/block)

    // rect first: its temporaries die before the 16 data floats go live
    const int4 rc = compute_rect_warp(b);

    // decode chunk -> (c, h, w0)
    int r0 = t - b * CPI;
    int c  = r0 / CPC;
    int r1 = r0 - c * CPC;
    int h  = r1 / CPR;
    int w0 = (r1 - h * CPR) << 4;

    // front-batch the 4 vector loads (MLP_p1 = 4, the proven sweet spot)
    alignas(16) float o[16];
    float4* ov4 = reinterpret_cast<float4*>(o);
    const float4* xp = x + (size_t)t * 4;
    ov4[0] = xp[0];
    ov4[1] = xp[1];
    ov4[2] = xp[2];
    ov4[3] = xp[3];

    float inv  = 1.0f / __ldg(&stdv[c]);
    float bias = -__ldg(&mean[c]) * inv;

    #pragma unroll
    for (int j = 0; j < 16; ++j)
        o[j] = fmaf(o[j], inv, bias);

    // row-range + column-overlap test once per thread; rare path per-lane
    if (h >= rc.x && h < rc.y && w0 + 15 >= rc.z && w0 < rc.w) {
        unsigned i0 = (unsigned)t * 16u;
        #pragma unroll
        for (int j = 0; j < 16; ++j) {
            int w = w0 + j;
            if (w >= rc.z && w < rc.w) o[j] = noise_at(i0 + (unsigned)j);
        }
    }

    float4* op = out + (size_t)t * 4;
    __stcs(op + 0, ov4[0]);
    __stcs(op + 1, ov4[1]);
    __stcs(op + 2, ov4[2]);
    __stcs(op + 3, ov4[3]);
}

// ---------------------------------------------------------------------------
// Launch
// ---------------------------------------------------------------------------
extern "C" void kernel_launch(void* const* d_in, const int* in_sizes, int n_in,
                              void* d_out, int out_size) {
    const float4* x   = (const float4*)d_in[0];
    const float*  mn  = (const float*)d_in[1];
    const float*  sd  = (const float*)d_in[2];
    float4*       out = (float4*)d_out;

    erase_kernel<<<NBLK, BLK>>>(x, mn, sd, out);
}